// round 14
// baseline (speedup 1.0000x reference)
#include <cuda_runtime.h>
#include <cuda_fp16.h>
#include <cstdint>

#define HH 768
#define NN 64
#define LSEQ 2048
#define Q 64
#define NCH 32
#define NTHREADS 512
#define NBLK HH

typedef unsigned int u32;
typedef unsigned short u16;

// ---------------- per-h panel image in gmem (built by panel_kernel) ----------------
// [0, 18432)      W fp16, 128 rows x stride 144
// [18432, 35840)  V fp16, 64 rows x stride 272
// [35840, 45056)  T fp16, 64 rows x stride 144
// [45056, 45568)  aq f32, 128 values
#define IMG_W    0
#define IMG_V    18432
#define IMG_T    35840
#define IMG_AQ   45056
#define IMG_BYTES 45568
__device__ __align__(16) unsigned char g_img[(size_t)HH * IMG_BYTES];

// ---------------- main-kernel smem layout (bytes), 2 CTAs/SM ----------------
#define OFF_AQ   1792         // 128 f32
#define OFF_U    2304         // U fp16: 128 x 144
#define OFF_PS   20736        // St fp16 128x272 -> Y fp32 128x272
#define OFF_W    55552        // W fp16 128x144 -> V fp16 64x272
#define OFF_R    73984        // R fp16 packed 128x268 -> T fp16 64x144 (post-scan)
#define RSTRB    268
#define OFF_T    OFF_R
#define SMEM_BYTES 108288

#define PSTR 130

// ---------------- helpers ----------------
__device__ __forceinline__ u32 smem_u32(const void* p) {
    u32 a;
    asm("{ .reg .u64 t; cvta.to.shared.u64 t, %1; cvt.u32.u64 %0, t; }" : "=r"(a) : "l"(p));
    return a;
}
__device__ __forceinline__ void ldsm_x4(u32 addr, u32& r0, u32& r1, u32& r2, u32& r3) {
    asm volatile("ldmatrix.sync.aligned.m8n8.x4.shared.b16 {%0,%1,%2,%3}, [%4];"
                 : "=r"(r0), "=r"(r1), "=r"(r2), "=r"(r3) : "r"(addr));
}
__device__ __forceinline__ void mma16816(float* d, u32 a0, u32 a1, u32 a2, u32 a3,
                                         u32 b0, u32 b1) {
    asm volatile("mma.sync.aligned.m16n8k16.row.col.f32.f16.f16.f32 "
                 "{%0,%1,%2,%3}, {%4,%5,%6,%7}, {%8,%9}, {%0,%1,%2,%3};"
                 : "+f"(d[0]), "+f"(d[1]), "+f"(d[2]), "+f"(d[3])
                 : "r"(a0), "r"(a1), "r"(a2), "r"(a3), "r"(b0), "r"(b1));
}
__device__ __forceinline__ u16 hf(float v) {
    return __half_as_ushort(__float2half_rn(v));
}
__device__ __forceinline__ float lo16(u32 w) {
    return __half2float(__ushort_as_half((u16)(w & 0xFFFFu)));
}
__device__ __forceinline__ float hi16(u32 w) {
    return __half2float(__ushort_as_half((u16)(w >> 16)));
}

// ---------------- Kernel 0: derive params + build all u-independent panels ----------------
__global__ void __launch_bounds__(256)
panel_kernel(const float* __restrict__ log_neg_real,
             const float* __restrict__ imag,
             const float* __restrict__ B_re,
             const float* __restrict__ B_im,
             const float* __restrict__ C_re,
             const float* __restrict__ C_im,
             const float* __restrict__ log_dt) {
    __shared__ float P[65 * PSTR];
    __shared__ float2 bbs[NN], ccs[NN], kms[NN];
    __shared__ float kl[Q];

    const int h = blockIdx.x;
    const int tid = threadIdx.x;
    unsigned char* img = g_img + (size_t)h * IMG_BYTES;

    // derive per-mode params + serial powers P[0..8]
    if (tid < NN) {
        const int n = tid, idx = h * NN + n;
        float lre = -expf(log_neg_real[idx]);
        float lim = imag[idx];
        float dt  = expf(log_dt[h]);
        float zre = lre * dt, zim = lim * dt;
        float ea = expf(zre);
        float sn, cs; sincosf(zim, &sn, &cs);
        float Are = ea * cs, Aim = ea * sn;

        float dre = Are - 1.0f, dim = Aim;
        float den = lre * lre + lim * lim;
        float ire = lre / den, iim = -lim / den;
        float tre = dre * ire - dim * iim;
        float tim = dre * iim + dim * ire;
        float br = B_re[idx], bi = B_im[idx];
        float Bbre = tre * br - tim * bi;
        float Bbim = tre * bi + tim * br;
        float cr = C_re[idx], ci = C_im[idx];

        bbs[n] = make_float2(Bbre, Bbim);
        ccs[n] = make_float2(cr, ci);
        kms[n] = make_float2(cr * Bbre - ci * Bbim, cr * Bbim + ci * Bbre);

        ((float2*)&P[0 * PSTR])[n] = make_float2(1.0f, 0.0f);
        ((float2*)&P[1 * PSTR])[n] = make_float2(Are, Aim);
        float pre = Are, pim = Aim;
        #pragma unroll
        for (int l = 2; l <= 8; ++l) {
            float nre = pre * Are - pim * Aim;
            float nim = pre * Aim + pim * Are;
            pre = nre; pim = nim;
            ((float2*)&P[l * PSTR])[n] = make_float2(pre, pim);
        }
    }
    __syncthreads();

    // doubling rounds m = 8, 16, 32
    #pragma unroll 1
    for (int m = 8; m < Q; m <<= 1) {
        for (int idx = tid; idx < m * 64; idx += 256) {
            int dl = idx >> 6, n = idx & 63;
            int l = m + 1 + dl;
            float2 am = ((const float2*)&P[m * PSTR])[n];
            float2 bm = ((const float2*)&P[(l - m) * PSTR])[n];
            ((float2*)&P[l * PSTR])[n] =
                make_float2(am.x * bm.x - am.y * bm.y, am.x * bm.y + am.y * bm.x);
        }
        __syncthreads();
    }

    // kl[l] = Re(sum_n K_n A^l), 4 lanes per l; aq -> image
    {
        const int l = tid >> 2, part = tid & 3;
        float acc = 0.0f;
        #pragma unroll
        for (int k = 0; k < 16; ++k) {
            int n = part * 16 + k;
            float2 pp = ((const float2*)&P[l * PSTR])[n];
            float2 km = kms[n];
            acc += km.x * pp.x - km.y * pp.y;
        }
        acc += __shfl_down_sync(0xFFFFFFFFu, acc, 2, 4);
        acc += __shfl_down_sync(0xFFFFFFFFu, acc, 1, 4);
        if (part == 0) kl[l] = acc;
        if (tid < 128) ((float*)(img + IMG_AQ))[tid] = P[Q * PSTR + tid];
    }
    __syncthreads();

    // W: rows r=2n/2n+1, cols j -> Re/Im(A^{63-j} Bbar)
    for (int idx = tid; idx < 128 * 32; idx += 256) {
        int r = idx >> 5, jp = idx & 31, n = r >> 1;
        int j0 = jp * 2;
        float2 p0 = ((const float2*)&P[(Q - 1 - j0) * PSTR])[n];
        float2 p1 = ((const float2*)&P[(Q - 2 - j0) * PSTR])[n];
        float2 bb = bbs[n];
        float v0, v1;
        if (r & 1) { v0 = p0.x * bb.y + p0.y * bb.x; v1 = p1.x * bb.y + p1.y * bb.x; }
        else       { v0 = p0.x * bb.x - p0.y * bb.y; v1 = p1.x * bb.x - p1.y * bb.y; }
        *(u32*)(img + IMG_W + (u32)(r * 144 + jp * 4)) =
            (u32)hf(v0) | ((u32)hf(v1) << 16);
    }
    // V: row i, packed (re, -im) of C * A^{i+1}
    for (int idx = tid; idx < 64 * 64; idx += 256) {
        int i = idx >> 6, n = idx & 63;
        float2 p = ((const float2*)&P[(i + 1) * PSTR])[n];
        float2 cc = ccs[n];
        float v0 = cc.x * p.x - cc.y * p.y;
        float v1 = -(cc.x * p.y + cc.y * p.x);
        *(u32*)(img + IMG_V + (u32)(i * 272 + 4 * n)) =
            (u32)hf(v0) | ((u32)hf(v1) << 16);
    }
    // T: Toeplitz kernel rows
    for (int idx = tid; idx < 64 * 32; idx += 256) {
        int i = idx >> 5, jp = idx & 31;
        int j0 = jp * 2;
        float v0 = (i >= j0) ? kl[i - j0] : 0.0f;
        float v1 = (i >= j0 + 1) ? kl[i - j0 - 1] : 0.0f;
        *(u32*)(img + IMG_T + (u32)(i * 144 + jp * 4)) =
            (u32)hf(v0) | ((u32)hf(v1) << 16);
    }
}

// ---------------- Kernel 1: GEMM + scan + epilogue only ----------------
__global__ void __launch_bounds__(NTHREADS, 2)
ssm_mma_kernel(const float* __restrict__ u,
               const float* __restrict__ Dv,
               float* __restrict__ y) {
    extern __shared__ char smem[];
    const u32 sbase = smem_u32(smem);
    const int tid = threadIdx.x;
    const int wid = tid >> 5;
    const int lane = tid & 31;
    const int h = blockIdx.x;
    const unsigned char* img = g_img + (size_t)h * IMG_BYTES;

    float* aq = (float*)(smem + OFF_AQ);

    // ---- Prologue: load u -> fp16 U panel; flat-copy W image + aq ----
    {
        const float4* u4 = (const float4*)u;
        for (int idx = tid; idx < 2048; idx += NTHREADS) {
            int b = idx >> 9, l4 = idx & 511;
            float4 v = u4[((size_t)b * HH + h) * 512 + (u32)l4];
            int c = (l4 >> 4) & 31, j = (l4 & 15) * 4;
            int col = b * 32 + c;
            u32 p0 = (u32)hf(v.x) | ((u32)hf(v.y) << 16);
            u32 p1 = (u32)hf(v.z) | ((u32)hf(v.w) << 16);
            *(uint2*)(smem + OFF_U + (u32)(col * 144 + j * 2)) = make_uint2(p0, p1);
        }
        const float4* ws = (const float4*)(img + IMG_W);
        float4* wd = (float4*)(smem + OFF_W);
        for (int idx = tid; idx < 1152; idx += NTHREADS) wd[idx] = ws[idx];
        if (tid < 128) aq[tid] = ((const float*)(img + IMG_AQ))[tid];
    }
    __syncthreads();

    // ---- G1: S_raw = W * U^T, write R fp16 packed [r][colpair] ----
    {
        const int wm = wid & 3, wn = wid >> 2;
        float acc[2][4][4];
        #pragma unroll
        for (int mt = 0; mt < 2; ++mt)
            #pragma unroll
            for (int nt = 0; nt < 4; ++nt)
                #pragma unroll
                for (int r = 0; r < 4; ++r) acc[mt][nt][r] = 0.0f;

        #pragma unroll
        for (int kt = 0; kt < 4; ++kt) {
            const int kb = kt * 32;
            u32 af[2][4], bf[4][2];
            #pragma unroll
            for (int mt = 0; mt < 2; ++mt) {
                int row = wm * 32 + mt * 16 + (lane & 15);
                u32 ad = sbase + OFF_W + (u32)(row * 144 + kb + (lane >> 4) * 16);
                ldsm_x4(ad, af[mt][0], af[mt][1], af[mt][2], af[mt][3]);
            }
            #pragma unroll
            for (int ntp = 0; ntp < 2; ++ntp) {
                int row = wn * 32 + ntp * 16 + ((lane >> 3) & 1) * 8 + (lane & 7);
                u32 bd = sbase + OFF_U + (u32)(row * 144 + kb + (lane >> 4) * 16);
                u32 q0, q1, q2, q3;
                ldsm_x4(bd, q0, q1, q2, q3);
                bf[2 * ntp][0] = q0; bf[2 * ntp][1] = q2;
                bf[2 * ntp + 1][0] = q1; bf[2 * ntp + 1][1] = q3;
            }
            #pragma unroll
            for (int mt = 0; mt < 2; ++mt)
                #pragma unroll
                for (int nt = 0; nt < 4; ++nt)
                    mma16816(acc[mt][nt], af[mt][0], af[mt][1], af[mt][2], af[mt][3],
                             bf[nt][0], bf[nt][1]);
        }
        #pragma unroll
        for (int mt = 0; mt < 2; ++mt)
            #pragma unroll
            for (int nt = 0; nt < 4; ++nt) {
                int r0 = wm * 32 + mt * 16 + (lane >> 2);
                int cp = wn * 16 + nt * 4 + (lane & 3);
                u32 v01 = (u32)hf(acc[mt][nt][0]) | ((u32)hf(acc[mt][nt][1]) << 16);
                u32 v23 = (u32)hf(acc[mt][nt][2]) | ((u32)hf(acc[mt][nt][3]) << 16);
                *(u32*)(smem + OFF_R + (u32)(r0 * RSTRB + cp * 4)) = v01;
                *(u32*)(smem + OFF_R + (u32)((r0 + 8) * RSTRB + cp * 4)) = v23;
            }
    }
    __syncthreads();

    // ---- Scan (warps 0-7) CONCURRENT WITH V copy (warps 8-15, over dead W) ----
    if (tid < 256) {
        const int n = tid & 63, b = tid >> 6;
        const float ar = aq[2 * n], ai = aq[2 * n + 1];
        float sre = 0.0f, sim = 0.0f;
        #pragma unroll 1
        for (int c4 = 0; c4 < 8; ++c4) {
            const int c0 = b * 32 + c4 * 4;
            const u32 cpb = (u32)((b * 16 + c4 * 2) * 4);
            u32 wre0 = *(const u32*)(smem + OFF_R + (u32)((2 * n) * RSTRB) + cpb);
            u32 wre1 = *(const u32*)(smem + OFF_R + (u32)((2 * n) * RSTRB) + cpb + 4);
            u32 wim0 = *(const u32*)(smem + OFF_R + (u32)((2 * n + 1) * RSTRB) + cpb);
            u32 wim1 = *(const u32*)(smem + OFF_R + (u32)((2 * n + 1) * RSTRB) + cpb + 4);
            float re0 = lo16(wre0), re1 = hi16(wre0), re2 = lo16(wre1), re3 = hi16(wre1);
            float im0 = lo16(wim0), im1 = hi16(wim0), im2 = lo16(wim1), im3 = hi16(wim1);
            #pragma unroll
            for (int q = 0; q < 4; ++q) {
                *(u32*)(smem + OFF_PS + (u32)((c0 + q) * 272 + 4 * n)) =
                    (u32)hf(sre) | ((u32)hf(sim) << 16);
                float rr = (q == 0) ? re0 : (q == 1) ? re1 : (q == 2) ? re2 : re3;
                float ii = (q == 0) ? im0 : (q == 1) ? im1 : (q == 2) ? im2 : im3;
                float nre = ar * sre - ai * sim + rr;
                float nim = ar * sim + ai * sre + ii;
                sre = nre; sim = nim;
            }
        }
    } else {
        const float4* vs = (const float4*)(img + IMG_V);
        float4* vd = (float4*)(smem + OFF_W);
        for (int idx = tid - 256; idx < 1088; idx += 256) vd[idx] = vs[idx];
    }
    __syncthreads();   // R dead -> T overlays it

    // ---- Copy T image (over dead R) ----
    {
        const float4* ts = (const float4*)(img + IMG_T);
        float4* td = (float4*)(smem + OFF_T);
        for (int idx = tid; idx < 576; idx += NTHREADS) td[idx] = ts[idx];
    }
    __syncthreads();

    // ---- G2: Y[64 x 128] = T*U^T (K64) + V*St^T (K128) ----
    {
        const int wm = wid & 3, wn = wid >> 2;
        float acc[4][4];
        #pragma unroll
        for (int nt = 0; nt < 4; ++nt)
            #pragma unroll
            for (int r = 0; r < 4; ++r) acc[nt][r] = 0.0f;

        #pragma unroll
        for (int kt = 0; kt < 4; ++kt) {
            const int kb = kt * 32;
            u32 af[4], bf[4][2];
            {
                int row = wm * 16 + (lane & 15);
                u32 ad = sbase + OFF_T + (u32)(row * 144 + kb + (lane >> 4) * 16);
                ldsm_x4(ad, af[0], af[1], af[2], af[3]);
            }
            #pragma unroll
            for (int ntp = 0; ntp < 2; ++ntp) {
                int row = wn * 32 + ntp * 16 + ((lane >> 3) & 1) * 8 + (lane & 7);
                u32 bd = sbase + OFF_U + (u32)(row * 144 + kb + (lane >> 4) * 16);
                u32 q0, q1, q2, q3;
                ldsm_x4(bd, q0, q1, q2, q3);
                bf[2 * ntp][0] = q0; bf[2 * ntp][1] = q2;
                bf[2 * ntp + 1][0] = q1; bf[2 * ntp + 1][1] = q3;
            }
            #pragma unroll
            for (int nt = 0; nt < 4; ++nt)
                mma16816(acc[nt], af[0], af[1], af[2], af[3], bf[nt][0], bf[nt][1]);
        }
        #pragma unroll 2
        for (int kt = 0; kt < 8; ++kt) {
            const int kb = kt * 32;
            u32 af[4], bf[4][2];
            {
                int row = wm * 16 + (lane & 15);
                u32 ad = sbase + OFF_W + (u32)(row * 272 + kb + (lane >> 4) * 16);
                ldsm_x4(ad, af[0], af[1], af[2], af[3]);
            }
            #pragma unroll
            for (int ntp = 0; ntp < 2; ++ntp) {
                int row = wn * 32 + ntp * 16 + ((lane >> 3) & 1) * 8 + (lane & 7);
                u32 bd = sbase + OFF_PS + (u32)(row * 272 + kb + (lane >> 4) * 16);
                u32 q0, q1, q2, q3;
                ldsm_x4(bd, q0, q1, q2, q3);
                bf[2 * ntp][0] = q0; bf[2 * ntp][1] = q2;
                bf[2 * ntp + 1][0] = q1; bf[2 * ntp + 1][1] = q3;
            }
            #pragma unroll
            for (int nt = 0; nt < 4; ++nt)
                mma16816(acc[nt], af[0], af[1], af[2], af[3], bf[nt][0], bf[nt][1]);
        }

        // ---- stage Y into St region (dead after G2): [col][i] fp32, stride 272 ----
        __syncthreads();
        #pragma unroll
        for (int nt = 0; nt < 4; ++nt)
            #pragma unroll
            for (int rg = 0; rg < 4; ++rg) {
                int i = wm * 16 + (lane >> 2) + ((rg >= 2) ? 8 : 0);
                int col = wn * 32 + nt * 8 + (lane & 3) * 2 + (rg & 1);
                *(float*)(smem + OFF_PS + (u32)(col * 272 + i * 4)) = acc[nt][rg];
            }
    }
    __syncthreads();

    // ---- Epilogue: coalesced y = Y + D*u (float4) ----
    {
        const float Dh = Dv[h];
        const float4* u4 = (const float4*)u;
        float4* y4 = (float4*)y;
        for (int idx = tid; idx < 2048; idx += NTHREADS) {
            int b = idx >> 9, l4 = idx & 511;
            int c = (l4 >> 4) & 31, jq = l4 & 15;
            int col = b * 32 + c;
            float4 uv = u4[((size_t)b * HH + h) * 512 + (u32)l4];
            float4 yv = *(const float4*)(smem + OFF_PS + (u32)(col * 272 + jq * 16));
            float4 ov;
            ov.x = yv.x + Dh * uv.x;
            ov.y = yv.y + Dh * uv.y;
            ov.z = yv.z + Dh * uv.z;
            ov.w = yv.w + Dh * uv.w;
            y4[((size_t)b * HH + h) * 512 + (u32)l4] = ov;
        }
    }
}

extern "C" void kernel_launch(void* const* d_in, const int* in_sizes, int n_in,
                              void* d_out, int out_size) {
    const float* u    = (const float*)d_in[0];
    const float* lnr  = (const float*)d_in[1];
    const float* im   = (const float*)d_in[2];
    const float* B_re = (const float*)d_in[3];
    const float* B_im = (const float*)d_in[4];
    const float* C_re = (const float*)d_in[5];
    const float* C_im = (const float*)d_in[6];
    const float* ldt  = (const float*)d_in[7];
    const float* Dv   = (const float*)d_in[8];
    float* y = (float*)d_out;

    static int attr_done = 0;
    if (!attr_done) {
        cudaFuncSetAttribute(ssm_mma_kernel,
                             cudaFuncAttributeMaxDynamicSharedMemorySize, SMEM_BYTES);
        attr_done = 1;
    }

    panel_kernel<<<NBLK, 256>>>(lnr, im, B_re, B_im, C_re, C_im, ldt);
    ssm_mma_kernel<<<NBLK, NTHREADS, SMEM_BYTES>>>(u, Dv, y);
}

// round 15
// speedup vs baseline: 1.1737x; 1.1737x over previous
#include <cuda_runtime.h>
#include <cuda_fp16.h>
#include <cstdint>

#define HH 768
#define NN 64
#define LSEQ 2048
#define Q 64
#define NCH 32
#define NTHREADS 512
#define NBLK HH

typedef unsigned int u32;
typedef unsigned short u16;

// ---------------- smem layout (bytes), 2 CTAs/SM ----------------
#define OFF_KL   0            // 64 f32
#define OFF_BBS  256          // 64 float2
#define OFF_CCS  768          // 64 float2
#define OFF_KMS  1280         // 64 float2
#define OFF_AQ   1792         // 128 f32
#define OFF_U    2304         // U fp16: 128 x 144
#define OFF_PS   20736        // P fp32 65x520 -> St fp16 128x272 -> Y fp32 128x272
#define PSTR     130
#define OFF_W    55552        // W fp16 128x144 -> V fp16 64x272
#define OFF_R    73984        // R fp16 packed 128x268 -> T fp16 64x144 (post-scan)
#define RSTRB    268
#define OFF_T    OFF_R
#define SMEM_BYTES 108288

// ---------------- helpers ----------------
__device__ __forceinline__ u32 smem_u32(const void* p) {
    u32 a;
    asm("{ .reg .u64 t; cvta.to.shared.u64 t, %1; cvt.u32.u64 %0, t; }" : "=r"(a) : "l"(p));
    return a;
}
__device__ __forceinline__ void ldsm_x4(u32 addr, u32& r0, u32& r1, u32& r2, u32& r3) {
    asm volatile("ldmatrix.sync.aligned.m8n8.x4.shared.b16 {%0,%1,%2,%3}, [%4];"
                 : "=r"(r0), "=r"(r1), "=r"(r2), "=r"(r3) : "r"(addr));
}
__device__ __forceinline__ void mma16816(float* d, u32 a0, u32 a1, u32 a2, u32 a3,
                                         u32 b0, u32 b1) {
    asm volatile("mma.sync.aligned.m16n8k16.row.col.f32.f16.f16.f32 "
                 "{%0,%1,%2,%3}, {%4,%5,%6,%7}, {%8,%9}, {%0,%1,%2,%3};"
                 : "+f"(d[0]), "+f"(d[1]), "+f"(d[2]), "+f"(d[3])
                 : "r"(a0), "r"(a1), "r"(a2), "r"(a3), "r"(b0), "r"(b1));
}
__device__ __forceinline__ u16 hf(float v) {
    return __half_as_ushort(__float2half_rn(v));
}
__device__ __forceinline__ float lo16(u32 w) {
    return __half2float(__ushort_as_half((u16)(w & 0xFFFFu)));
}
__device__ __forceinline__ float hi16(u32 w) {
    return __half2float(__ushort_as_half((u16)(w >> 16)));
}

// Per-(h,n) discretized params
__device__ float2 g_A[HH * NN];
__device__ float2 g_Bb[HH * NN];
__device__ float2 g_C[HH * NN];
__device__ float2 g_K[HH * NN];

// ---------------- Kernel 0: ZOH discretization ----------------
__global__ void setup_kernel(const float* __restrict__ log_neg_real,
                             const float* __restrict__ imag,
                             const float* __restrict__ B_re,
                             const float* __restrict__ B_im,
                             const float* __restrict__ C_re,
                             const float* __restrict__ C_im,
                             const float* __restrict__ log_dt) {
    int idx = blockIdx.x * blockDim.x + threadIdx.x;
    if (idx >= HH * NN) return;
    int h = idx >> 6;

    float lre = -expf(log_neg_real[idx]);
    float lim = imag[idx];
    float dt  = expf(log_dt[h]);

    float zre = lre * dt, zim = lim * dt;
    float ea = expf(zre);
    float sn, cs; sincosf(zim, &sn, &cs);
    float Are = ea * cs, Aim = ea * sn;

    float dre = Are - 1.0f, dim = Aim;
    float den = lre * lre + lim * lim;
    float ire = lre / den, iim = -lim / den;
    float tre = dre * ire - dim * iim;
    float tim = dre * iim + dim * ire;
    float br = B_re[idx], bi = B_im[idx];
    float Bbre = tre * br - tim * bi;
    float Bbim = tre * bi + tim * br;

    float cr = C_re[idx], ci = C_im[idx];

    g_A[idx]  = make_float2(Are, Aim);
    g_Bb[idx] = make_float2(Bbre, Bbim);
    g_C[idx]  = make_float2(cr, ci);
    g_K[idx]  = make_float2(cr * Bbre - ci * Bbim, cr * Bbim + ci * Bbre);
}

// ---------------- Kernel 1: fused chunked SSM on HMMA fp16, 2 CTAs/SM ----------------
__global__ void __launch_bounds__(NTHREADS, 2)
ssm_mma_kernel(const float* __restrict__ u,
               const float* __restrict__ Dv,
               float* __restrict__ y) {
    extern __shared__ char smem[];
    const u32 sbase = smem_u32(smem);
    const int tid = threadIdx.x;
    const int wid = tid >> 5;
    const int lane = tid & 31;
    const int h = blockIdx.x;

    float*  aq  = (float*)(smem + OFF_AQ);
    float*  kl  = (float*)(smem + OFF_KL);
    float2* bbs = (float2*)(smem + OFF_BBS);
    float2* ccs = (float2*)(smem + OFF_CCS);
    float2* kms = (float2*)(smem + OFF_KMS);
    float*  P   = (float*)(smem + OFF_PS);

    // ---- Phase A0: params + serial powers P[0..16]; Phase D: load u -> fp16 U ----
    if (tid < NN) {
        const int n = tid;
        float2 a = g_A[h * NN + n];
        bbs[n] = g_Bb[h * NN + n];
        ccs[n] = g_C[h * NN + n];
        kms[n] = g_K[h * NN + n];
        ((float2*)&P[0 * PSTR])[n] = make_float2(1.0f, 0.0f);
        ((float2*)&P[1 * PSTR])[n] = a;
        float pre = a.x, pim = a.y;
        #pragma unroll
        for (int l = 2; l <= 16; ++l) {
            float nre = pre * a.x - pim * a.y;
            float nim = pre * a.y + pim * a.x;
            pre = nre; pim = nim;
            ((float2*)&P[l * PSTR])[n] = make_float2(pre, pim);
        }
    }
    {
        const float4* u4 = (const float4*)u;
        for (int idx = tid; idx < 2048; idx += NTHREADS) {
            int b = idx >> 9, l4 = idx & 511;
            float4 v = u4[((size_t)b * HH + h) * 512 + (u32)l4];
            int c = (l4 >> 4) & 31, j = (l4 & 15) * 4;
            int col = b * 32 + c;
            u32 p0 = (u32)hf(v.x) | ((u32)hf(v.y) << 16);
            u32 p1 = (u32)hf(v.z) | ((u32)hf(v.w) << 16);
            *(uint2*)(smem + OFF_U + (u32)(col * 144 + j * 2)) = make_uint2(p0, p1);
        }
    }
    __syncthreads();

    // ---- Phase A1: 2 doubling rounds m = 16, 32 ----
    #pragma unroll 1
    for (int m = 16; m < Q; m <<= 1) {
        for (int idx = tid; idx < m * 64; idx += NTHREADS) {
            int dl = idx >> 6, n = idx & 63;
            int l = m + 1 + dl;
            float2 am = ((const float2*)&P[m * PSTR])[n];
            float2 bm = ((const float2*)&P[(l - m) * PSTR])[n];
            ((float2*)&P[l * PSTR])[n] =
                make_float2(am.x * bm.x - am.y * bm.y, am.x * bm.y + am.y * bm.x);
        }
        __syncthreads();
    }

    // ---- Phase B: kl[l]; aq = A^Q ----
    {
        const int l = tid >> 3, part = tid & 7;
        float acc = 0.0f;
        #pragma unroll
        for (int k = 0; k < 8; ++k) {
            int n = part * 8 + k;
            float2 pp = ((const float2*)&P[l * PSTR])[n];
            float2 km = kms[n];
            acc += km.x * pp.x - km.y * pp.y;
        }
        acc += __shfl_down_sync(0xFFFFFFFFu, acc, 4, 8);
        acc += __shfl_down_sync(0xFFFFFFFFu, acc, 2, 8);
        acc += __shfl_down_sync(0xFFFFFFFFu, acc, 1, 8);
        if (part == 0) kl[l] = acc;
        if (tid < 128) aq[tid] = P[Q * PSTR + tid];
    }
    // ---- Phase C1: build W (single fp16), 2 cols per thread ----
    for (int idx = tid; idx < 128 * 32; idx += NTHREADS) {
        int r = idx >> 5, jp = idx & 31, n = r >> 1;
        int j0 = jp * 2;
        float2 p0 = ((const float2*)&P[(Q - 1 - j0) * PSTR])[n];
        float2 p1 = ((const float2*)&P[(Q - 2 - j0) * PSTR])[n];
        float2 bb = bbs[n];
        float v0, v1;
        if (r & 1) { v0 = p0.x * bb.y + p0.y * bb.x; v1 = p1.x * bb.y + p1.y * bb.x; }
        else       { v0 = p0.x * bb.x - p0.y * bb.y; v1 = p1.x * bb.x - p1.y * bb.y; }
        *(u32*)(smem + OFF_W + (u32)(r * 144 + jp * 4)) =
            (u32)hf(v0) | ((u32)hf(v1) << 16);
    }
    __syncthreads();

    // ---- G1: S_raw = W * U^T (single product), write R fp16 packed [r][colpair] ----
    {
        const int wm = wid & 3, wn = wid >> 2;
        float acc[2][4][4];
        #pragma unroll
        for (int mt = 0; mt < 2; ++mt)
            #pragma unroll
            for (int nt = 0; nt < 4; ++nt)
                #pragma unroll
                for (int r = 0; r < 4; ++r) acc[mt][nt][r] = 0.0f;

        #pragma unroll
        for (int kt = 0; kt < 4; ++kt) {
            const int kb = kt * 32;
            u32 af[2][4], bf[4][2];
            #pragma unroll
            for (int mt = 0; mt < 2; ++mt) {
                int row = wm * 32 + mt * 16 + (lane & 15);
                u32 ad = sbase + OFF_W + (u32)(row * 144 + kb + (lane >> 4) * 16);
                ldsm_x4(ad, af[mt][0], af[mt][1], af[mt][2], af[mt][3]);
            }
            #pragma unroll
            for (int ntp = 0; ntp < 2; ++ntp) {
                int row = wn * 32 + ntp * 16 + ((lane >> 3) & 1) * 8 + (lane & 7);
                u32 bd = sbase + OFF_U + (u32)(row * 144 + kb + (lane >> 4) * 16);
                u32 q0, q1, q2, q3;
                ldsm_x4(bd, q0, q1, q2, q3);
                bf[2 * ntp][0] = q0; bf[2 * ntp][1] = q2;
                bf[2 * ntp + 1][0] = q1; bf[2 * ntp + 1][1] = q3;
            }
            #pragma unroll
            for (int mt = 0; mt < 2; ++mt)
                #pragma unroll
                for (int nt = 0; nt < 4; ++nt)
                    mma16816(acc[mt][nt], af[mt][0], af[mt][1], af[mt][2], af[mt][3],
                             bf[nt][0], bf[nt][1]);
        }
        #pragma unroll
        for (int mt = 0; mt < 2; ++mt)
            #pragma unroll
            for (int nt = 0; nt < 4; ++nt) {
                int r0 = wm * 32 + mt * 16 + (lane >> 2);
                int cp = wn * 16 + nt * 4 + (lane & 3);
                u32 v01 = (u32)hf(acc[mt][nt][0]) | ((u32)hf(acc[mt][nt][1]) << 16);
                u32 v23 = (u32)hf(acc[mt][nt][2]) | ((u32)hf(acc[mt][nt][3]) << 16);
                *(u32*)(smem + OFF_R + (u32)(r0 * RSTRB + cp * 4)) = v01;
                *(u32*)(smem + OFF_R + (u32)((r0 + 8) * RSTRB + cp * 4)) = v23;
            }
    }
    __syncthreads();

    // ---- Phase C2: build V (over W, dead); P still alive ----
    for (int idx = tid; idx < 64 * 64; idx += NTHREADS) {
        int i = idx >> 6, n = idx & 63;
        float2 p = ((const float2*)&P[(i + 1) * PSTR])[n];
        float2 cc = ccs[n];
        float v0 = cc.x * p.x - cc.y * p.y;
        float v1 = -(cc.x * p.y + cc.y * p.x);
        *(u32*)(smem + OFF_W + (u32)(i * 272 + 4 * n)) =
            (u32)hf(v0) | ((u32)hf(v1) << 16);
    }
    __syncthreads();   // V done; P dead -> scan may overwrite PS with St

    // ---- Phase F: 32-chunk state scan (256 threads); St overlays P ----
    if (tid < 256) {
        const int n = tid & 63, b = tid >> 6;
        const float ar = aq[2 * n], ai = aq[2 * n + 1];
        float sre = 0.0f, sim = 0.0f;
        #pragma unroll 1
        for (int c4 = 0; c4 < 8; ++c4) {
            const int c0 = b * 32 + c4 * 4;
            const u32 cpb = (u32)((b * 16 + c4 * 2) * 4);
            u32 wre0 = *(const u32*)(smem + OFF_R + (u32)((2 * n) * RSTRB) + cpb);
            u32 wre1 = *(const u32*)(smem + OFF_R + (u32)((2 * n) * RSTRB) + cpb + 4);
            u32 wim0 = *(const u32*)(smem + OFF_R + (u32)((2 * n + 1) * RSTRB) + cpb);
            u32 wim1 = *(const u32*)(smem + OFF_R + (u32)((2 * n + 1) * RSTRB) + cpb + 4);
            float re0 = lo16(wre0), re1 = hi16(wre0), re2 = lo16(wre1), re3 = hi16(wre1);
            float im0 = lo16(wim0), im1 = hi16(wim0), im2 = lo16(wim1), im3 = hi16(wim1);
            #pragma unroll
            for (int q = 0; q < 4; ++q) {
                *(u32*)(smem + OFF_PS + (u32)((c0 + q) * 272 + 4 * n)) =
                    (u32)hf(sre) | ((u32)hf(sim) << 16);
                float rr = (q == 0) ? re0 : (q == 1) ? re1 : (q == 2) ? re2 : re3;
                float ii = (q == 0) ? im0 : (q == 1) ? im1 : (q == 2) ? im2 : im3;
                float nre = ar * sre - ai * sim + rr;
                float nim = ar * sim + ai * sre + ii;
                sre = nre; sim = nim;
            }
        }
    }
    __syncthreads();   // R dead -> T overlays it

    // ---- Phase C3: build T (stride 144, conflict-free ldmatrix) ----
    for (int idx = tid; idx < 64 * 32; idx += NTHREADS) {
        int i = idx >> 5, jp = idx & 31;
        int j0 = jp * 2;
        float v0 = (i >= j0) ? kl[i - j0] : 0.0f;
        float v1 = (i >= j0 + 1) ? kl[i - j0 - 1] : 0.0f;
        *(u32*)(smem + OFF_T + (u32)(i * 144 + jp * 4)) =
            (u32)hf(v0) | ((u32)hf(v1) << 16);
    }
    __syncthreads();

    // ---- G2: Y[64 x 128] = T*U^T (K64) + V*St^T (K128), single products ----
    {
        const int wm = wid & 3, wn = wid >> 2;
        float acc[4][4];
        #pragma unroll
        for (int nt = 0; nt < 4; ++nt)
            #pragma unroll
            for (int r = 0; r < 4; ++r) acc[nt][r] = 0.0f;

        #pragma unroll
        for (int kt = 0; kt < 4; ++kt) {
            const int kb = kt * 32;
            u32 af[4], bf[4][2];
            {
                int row = wm * 16 + (lane & 15);
                u32 ad = sbase + OFF_T + (u32)(row * 144 + kb + (lane >> 4) * 16);
                ldsm_x4(ad, af[0], af[1], af[2], af[3]);
            }
            #pragma unroll
            for (int ntp = 0; ntp < 2; ++ntp) {
                int row = wn * 32 + ntp * 16 + ((lane >> 3) & 1) * 8 + (lane & 7);
                u32 bd = sbase + OFF_U + (u32)(row * 144 + kb + (lane >> 4) * 16);
                u32 q0, q1, q2, q3;
                ldsm_x4(bd, q0, q1, q2, q3);
                bf[2 * ntp][0] = q0; bf[2 * ntp][1] = q2;
                bf[2 * ntp + 1][0] = q1; bf[2 * ntp + 1][1] = q3;
            }
            #pragma unroll
            for (int nt = 0; nt < 4; ++nt)
                mma16816(acc[nt], af[0], af[1], af[2], af[3], bf[nt][0], bf[nt][1]);
        }
        #pragma unroll 2
        for (int kt = 0; kt < 8; ++kt) {
            const int kb = kt * 32;
            u32 af[4], bf[4][2];
            {
                int row = wm * 16 + (lane & 15);
                u32 ad = sbase + OFF_W + (u32)(row * 272 + kb + (lane >> 4) * 16);
                ldsm_x4(ad, af[0], af[1], af[2], af[3]);
            }
            #pragma unroll
            for (int ntp = 0; ntp < 2; ++ntp) {
                int row = wn * 32 + ntp * 16 + ((lane >> 3) & 1) * 8 + (lane & 7);
                u32 bd = sbase + OFF_PS + (u32)(row * 272 + kb + (lane >> 4) * 16);
                u32 q0, q1, q2, q3;
                ldsm_x4(bd, q0, q1, q2, q3);
                bf[2 * ntp][0] = q0; bf[2 * ntp][1] = q2;
                bf[2 * ntp + 1][0] = q1; bf[2 * ntp + 1][1] = q3;
            }
            #pragma unroll
            for (int nt = 0; nt < 4; ++nt)
                mma16816(acc[nt], af[0], af[1], af[2], af[3], bf[nt][0], bf[nt][1]);
        }

        // ---- stage Y into St region (dead after G2): [col][i] fp32, stride 272 ----
        __syncthreads();
        #pragma unroll
        for (int nt = 0; nt < 4; ++nt)
            #pragma unroll
            for (int rg = 0; rg < 4; ++rg) {
                int i = wm * 16 + (lane >> 2) + ((rg >= 2) ? 8 : 0);
                int col = wn * 32 + nt * 8 + (lane & 3) * 2 + (rg & 1);
                *(float*)(smem + OFF_PS + (u32)(col * 272 + i * 4)) = acc[nt][rg];
            }
    }
    __syncthreads();

    // ---- Epilogue: coalesced y = Y + D*u, u taken from fp16 U panel in smem ----
    {
        const float Dh = Dv[h];
        float4* y4 = (float4*)y;
        for (int idx = tid; idx < 2048; idx += NTHREADS) {
            int b = idx >> 9, l4 = idx & 511;
            int c = (l4 >> 4) & 31, jq = l4 & 15;
            int col = b * 32 + c;
            uint2 up = *(const uint2*)(smem + OFF_U + (u32)(col * 144 + jq * 8));
            float4 yv = *(const float4*)(smem + OFF_PS + (u32)(col * 272 + jq * 16));
            float4 ov;
            ov.x = yv.x + Dh * lo16(up.x);
            ov.y = yv.y + Dh * hi16(up.x);
            ov.z = yv.z + Dh * lo16(up.y);
            ov.w = yv.w + Dh * hi16(up.y);
            y4[((size_t)b * HH + h) * 512 + (u32)l4] = ov;
        }
    }
}

extern "C" void kernel_launch(void* const* d_in, const int* in_sizes, int n_in,
                              void* d_out, int out_size) {
    const float* u    = (const float*)d_in[0];
    const float* lnr  = (const float*)d_in[1];
    const float* im   = (const float*)d_in[2];
    const float* B_re = (const float*)d_in[3];
    const float* B_im = (const float*)d_in[4];
    const float* C_re = (const float*)d_in[5];
    const float* C_im = (const float*)d_in[6];
    const float* ldt  = (const float*)d_in[7];
    const float* Dv   = (const float*)d_in[8];
    float* y = (float*)d_out;

    static int attr_done = 0;
    if (!attr_done) {
        cudaFuncSetAttribute(ssm_mma_kernel,
                             cudaFuncAttributeMaxDynamicSharedMemorySize, SMEM_BYTES);
        attr_done = 1;
    }

    setup_kernel<<<(HH * NN + 255) / 256, 256>>>(lnr, im, B_re, B_im, C_re, C_im, ldt);
    ssm_mma_kernel<<<NBLK, NTHREADS, SMEM_BYTES>>>(u, Dv, y);
}